// round 10
// baseline (speedup 1.0000x reference)
#include <cuda_runtime.h>
#include <math.h>

#define BB 16
#define MM 256
#define TT 128
#define DD 512
#define HH 8
#define LLAYERS 4
#define VV 32000
#define HDIM 64
#define BT (BB*TT)      /* 2048 */
#define BMEM (BB*MM)    /* 4096 */
#define NEGINF -1e9f

// ------------------------- scratch (device globals) -------------------------
__device__ float g_x  [BT * DD];
__device__ float g_h  [BT * DD];
__device__ float g_q  [BT * DD];
__device__ float g_qkv[BT * 3 * DD];
__device__ float g_kv [BMEM * 2 * DD];
__device__ float g_sc [BB * HH * TT * MM];
__device__ float g_ctx[BT * DD];
__device__ float g_ffn[BT * 4 * DD];
__device__ int   g_is64;

// ------------------------- dtype probe for targets -------------------------
// If targets are int64 (little-endian, values in [0,32000)), every odd int32
// word of the first 1024 elements is zero. If int32, they are random token
// ids — all-zero has probability ~(1/32000)^1000. Reads stay within 2048
// int32s, which is the buffer size even in the int32 case.
__global__ void detect_k(const int* __restrict__ t) {
    __shared__ int allzero;
    if (threadIdx.x == 0) allzero = 1;
    __syncthreads();
    for (int i = threadIdx.x; i < 1024; i += blockDim.x) {
        if (t[2 * i + 1] != 0) allzero = 0;   // benign race, only writes 0
    }
    __syncthreads();
    if (threadIdx.x == 0) g_is64 = allzero;
}

// ------------------------- embedding -------------------------
__global__ void embed_k(const int* __restrict__ tgt,
                        const float* __restrict__ tok,
                        const float* __restrict__ pos,
                        float* __restrict__ x) {
    int bt = blockIdx.x;
    int b = bt / TT, t = bt % TT;
    int idx;
    if (t == 0) {
        idx = VV;  // BOS
    } else {
        int j = b * TT + t - 1;
        idx = g_is64 ? tgt[2 * j] : tgt[j];
    }
    const float* tr = tok + (size_t)idx * DD;
    const float* pr = pos + (size_t)t * DD;
    float* xr = x + (size_t)bt * DD;
    for (int d = threadIdx.x * 4; d < DD; d += blockDim.x * 4) {
        float4 a = *(const float4*)(tr + d);
        float4 p = *(const float4*)(pr + d);
        a.x += p.x; a.y += p.y; a.z += p.z; a.w += p.w;
        *(float4*)(xr + d) = a;
    }
}

// ------------------------- layernorm (row of 512, 128 threads) -------------
__global__ void ln_k(const float* __restrict__ x,
                     const float* __restrict__ g,
                     const float* __restrict__ b,
                     float* __restrict__ o) {
    int row = blockIdx.x;
    int tid = threadIdx.x;
    const float* xr = x + (size_t)row * DD;
    int d = tid * 4;
    float4 v = *(const float4*)(xr + d);
    float s  = v.x + v.y + v.z + v.w;
    float sq = v.x * v.x + v.y * v.y + v.z * v.z + v.w * v.w;
    __shared__ float rs[32], rq[32];
    #pragma unroll
    for (int ofs = 16; ofs > 0; ofs >>= 1) {
        s  += __shfl_xor_sync(0xffffffffu, s, ofs);
        sq += __shfl_xor_sync(0xffffffffu, sq, ofs);
    }
    if ((tid & 31) == 0) { rs[tid >> 5] = s; rq[tid >> 5] = sq; }
    __syncthreads();
    float S = rs[0] + rs[1] + rs[2] + rs[3];
    float Q = rq[0] + rq[1] + rq[2] + rq[3];
    float mean = S * (1.0f / DD);
    float var  = Q * (1.0f / DD) - mean * mean;
    float rstd = rsqrtf(var + 1e-5f);
    float4 gg = *(const float4*)(g + d);
    float4 bb = *(const float4*)(b + d);
    float4 r;
    r.x = (v.x - mean) * rstd * gg.x + bb.x;
    r.y = (v.y - mean) * rstd * gg.y + bb.y;
    r.z = (v.z - mean) * rstd * gg.z + bb.z;
    r.w = (v.w - mean) * rstd * gg.w + bb.w;
    *(float4*)(o + (size_t)row * DD + d) = r;
}

// ------------------------- SGEMM: C = A[rows,K] @ W[K,Ncols] + epi ---------
// EPI: 0 = +bias, 1 = +bias+residual, 2 = +bias then exact GELU
// Requires: rows % 64 == 0 (via grid.y), Ncols % 64 == 0, K % 16 == 0.
template <int EPI>
__global__ void __launch_bounds__(256)
sgemm_k(const float* __restrict__ A, const float* __restrict__ W,
        const float* __restrict__ bias, const float* __restrict__ res,
        float* __restrict__ C, int Ncols, int K) {
    __shared__ float As[16][64];  // transposed: As[k][m]
    __shared__ float Bs[16][64];
    int tid = threadIdx.x;
    int tx = tid & 15, ty = tid >> 4;
    int rowBase = blockIdx.y * 64, colBase = blockIdx.x * 64;
    int am = tid >> 2, ak = (tid & 3) * 4;
    int bk = tid >> 4, bc = (tid & 15) * 4;
    const float* Ap = A + (size_t)(rowBase + am) * K + ak;
    const float* Wp = W + (size_t)bk * Ncols + colBase + bc;

    float acc[4][4];
    #pragma unroll
    for (int i = 0; i < 4; i++)
        #pragma unroll
        for (int j = 0; j < 4; j++) acc[i][j] = 0.0f;

    for (int k0 = 0; k0 < K; k0 += 16) {
        float4 av = *(const float4*)Ap; Ap += 16;
        float4 bv = *(const float4*)Wp; Wp += (size_t)16 * Ncols;
        __syncthreads();
        As[ak + 0][am] = av.x;
        As[ak + 1][am] = av.y;
        As[ak + 2][am] = av.z;
        As[ak + 3][am] = av.w;
        *(float4*)&Bs[bk][bc] = bv;
        __syncthreads();
        #pragma unroll
        for (int kk = 0; kk < 16; kk++) {
            float4 a4 = *(const float4*)&As[kk][ty * 4];
            float4 b4 = *(const float4*)&Bs[kk][tx * 4];
            float a[4] = {a4.x, a4.y, a4.z, a4.w};
            float b[4] = {b4.x, b4.y, b4.z, b4.w};
            #pragma unroll
            for (int i = 0; i < 4; i++)
                #pragma unroll
                for (int j = 0; j < 4; j++)
                    acc[i][j] = fmaf(a[i], b[j], acc[i][j]);
        }
    }

    int cBase = colBase + tx * 4;
    float4 bia = *(const float4*)(bias + cBase);
    #pragma unroll
    for (int i = 0; i < 4; i++) {
        int r = rowBase + ty * 4 + i;
        float4 v;
        v.x = acc[i][0] + bia.x;
        v.y = acc[i][1] + bia.y;
        v.z = acc[i][2] + bia.z;
        v.w = acc[i][3] + bia.w;
        if (EPI == 1) {
            float4 rr = *(const float4*)(res + (size_t)r * Ncols + cBase);
            v.x += rr.x; v.y += rr.y; v.z += rr.z; v.w += rr.w;
        }
        if (EPI == 2) {
            v.x = 0.5f * v.x * (1.0f + erff(v.x * 0.70710678118654752f));
            v.y = 0.5f * v.y * (1.0f + erff(v.y * 0.70710678118654752f));
            v.z = 0.5f * v.z * (1.0f + erff(v.z * 0.70710678118654752f));
            v.w = 0.5f * v.w * (1.0f + erff(v.w * 0.70710678118654752f));
        }
        *(float4*)(C + (size_t)r * Ncols + cBase) = v;
    }
}

// ------------------------- attention scores -------------------------
// S[bh, q, k] = scale * dot(Q[b,q,h,:], K[b,k,h,:]); causal mask optional.
// One block per (128-col tile, bh). Block 256 threads, 8x8 per thread.
__global__ void __launch_bounds__(256)
scores_k(const float* __restrict__ Qb, int qStride, size_t qBatch,
         const float* __restrict__ Kb, int kStride, size_t kBatch,
         int Lk, int causal, float* __restrict__ S) {
    int bh = blockIdx.y;
    int b = bh / HH, h = bh % HH;
    int k0 = blockIdx.x * 128;
    const float* Q  = Qb + (size_t)b * qBatch + h * HDIM;
    const float* Kp = Kb + (size_t)b * kBatch + h * HDIM;
    __shared__ float Qs[16][128];
    __shared__ float Ks[16][128];
    int tid = threadIdx.x;
    int tx = tid & 15, ty = tid >> 4;
    int lr = tid >> 1, ls = (tid & 1) * 8;

    float acc[8][8];
    #pragma unroll
    for (int i = 0; i < 8; i++)
        #pragma unroll
        for (int j = 0; j < 8; j++) acc[i][j] = 0.0f;

    for (int d0 = 0; d0 < HDIM; d0 += 16) {
        float4 qa = *(const float4*)(Q + (size_t)lr * qStride + d0 + ls);
        float4 qb = *(const float4*)(Q + (size_t)lr * qStride + d0 + ls + 4);
        float4 ka = *(const float4*)(Kp + (size_t)(k0 + lr) * kStride + d0 + ls);
        float4 kb = *(const float4*)(Kp + (size_t)(k0 + lr) * kStride + d0 + ls + 4);
        __syncthreads();
        Qs[ls + 0][lr] = qa.x; Qs[ls + 1][lr] = qa.y; Qs[ls + 2][lr] = qa.z; Qs[ls + 3][lr] = qa.w;
        Qs[ls + 4][lr] = qb.x; Qs[ls + 5][lr] = qb.y; Qs[ls + 6][lr] = qb.z; Qs[ls + 7][lr] = qb.w;
        Ks[ls + 0][lr] = ka.x; Ks[ls + 1][lr] = ka.y; Ks[ls + 2][lr] = ka.z; Ks[ls + 3][lr] = ka.w;
        Ks[ls + 4][lr] = kb.x; Ks[ls + 5][lr] = kb.y; Ks[ls + 6][lr] = kb.z; Ks[ls + 7][lr] = kb.w;
        __syncthreads();
        #pragma unroll
        for (int dd = 0; dd < 16; dd++) {
            float4 q0 = *(const float4*)&Qs[dd][ty * 8];
            float4 q1 = *(const float4*)&Qs[dd][ty * 8 + 4];
            float4 c0 = *(const float4*)&Ks[dd][tx * 8];
            float4 c1 = *(const float4*)&Ks[dd][tx * 8 + 4];
            float qv[8] = {q0.x, q0.y, q0.z, q0.w, q1.x, q1.y, q1.z, q1.w};
            float kv[8] = {c0.x, c0.y, c0.z, c0.w, c1.x, c1.y, c1.z, c1.w};
            #pragma unroll
            for (int i = 0; i < 8; i++)
                #pragma unroll
                for (int j = 0; j < 8; j++)
                    acc[i][j] = fmaf(qv[i], kv[j], acc[i][j]);
        }
    }
    const float scale = 0.125f;  // 1/sqrt(64)
    #pragma unroll
    for (int i = 0; i < 8; i++) {
        int q = ty * 8 + i;
        #pragma unroll
        for (int j = 0; j < 8; j++) {
            int kidx = k0 + tx * 8 + j;
            float v = acc[i][j] * scale;
            if (causal && kidx > q) v = NEGINF;
            S[((size_t)bh * TT + q) * Lk + kidx] = v;
        }
    }
}

// ------------------------- row softmax (in place) -------------------------
__global__ void softmax_k(float* __restrict__ S, int Lk) {
    int row = blockIdx.x;
    float* r = S + (size_t)row * Lk;
    int tid = threadIdx.x;  // 128
    __shared__ float red[32];

    float m = -3.4e38f;
    for (int i = tid; i < Lk; i += 128) m = fmaxf(m, r[i]);
    #pragma unroll
    for (int ofs = 16; ofs > 0; ofs >>= 1) m = fmaxf(m, __shfl_xor_sync(0xffffffffu, m, ofs));
    if ((tid & 31) == 0) red[tid >> 5] = m;
    __syncthreads();
    m = fmaxf(fmaxf(red[0], red[1]), fmaxf(red[2], red[3]));

    float s = 0.0f;
    for (int i = tid; i < Lk; i += 128) {
        float e = expf(r[i] - m);
        r[i] = e;
        s += e;
    }
    #pragma unroll
    for (int ofs = 16; ofs > 0; ofs >>= 1) s += __shfl_xor_sync(0xffffffffu, s, ofs);
    __syncthreads();
    if ((tid & 31) == 0) red[tid >> 5] = s;
    __syncthreads();
    s = red[0] + red[1] + red[2] + red[3];
    float inv = 1.0f / s;
    for (int i = tid; i < Lk; i += 128) r[i] *= inv;
}

// ------------------------- ctx = P @ V, written merged [B,T,D] -------------
__global__ void __launch_bounds__(256)
pv_k(const float* __restrict__ S, int Lk,
     const float* __restrict__ Vb, int vStride, size_t vBatch,
     float* __restrict__ O) {
    int bh = blockIdx.x;
    int b = bh / HH, h = bh % HH;
    const float* P  = S + (size_t)bh * TT * Lk;
    const float* Vp = Vb + (size_t)b * vBatch + h * HDIM;
    __shared__ float Ps[16][128];
    __shared__ float Vs[16][64];
    int tid = threadIdx.x;
    int tx = tid & 15, ty = tid >> 4;
    int pr = tid >> 1, ps = (tid & 1) * 8;
    int vk = tid >> 4, vc = (tid & 15) * 4;

    float acc[8][4];
    #pragma unroll
    for (int i = 0; i < 8; i++)
        #pragma unroll
        for (int j = 0; j < 4; j++) acc[i][j] = 0.0f;

    for (int k0 = 0; k0 < Lk; k0 += 16) {
        float4 pa = *(const float4*)(P + (size_t)pr * Lk + k0 + ps);
        float4 pb = *(const float4*)(P + (size_t)pr * Lk + k0 + ps + 4);
        float4 vv = *(const float4*)(Vp + (size_t)(k0 + vk) * vStride + vc);
        __syncthreads();
        Ps[ps + 0][pr] = pa.x; Ps[ps + 1][pr] = pa.y; Ps[ps + 2][pr] = pa.z; Ps[ps + 3][pr] = pa.w;
        Ps[ps + 4][pr] = pb.x; Ps[ps + 5][pr] = pb.y; Ps[ps + 6][pr] = pb.z; Ps[ps + 7][pr] = pb.w;
        *(float4*)&Vs[vk][vc] = vv;
        __syncthreads();
        #pragma unroll
        for (int kk = 0; kk < 16; kk++) {
            float4 p0 = *(const float4*)&Ps[kk][ty * 8];
            float4 p1 = *(const float4*)&Ps[kk][ty * 8 + 4];
            float4 v4 = *(const float4*)&Vs[kk][tx * 4];
            float pvv[8] = {p0.x, p0.y, p0.z, p0.w, p1.x, p1.y, p1.z, p1.w};
            float vvv[4] = {v4.x, v4.y, v4.z, v4.w};
            #pragma unroll
            for (int i = 0; i < 8; i++)
                #pragma unroll
                for (int j = 0; j < 4; j++)
                    acc[i][j] = fmaf(pvv[i], vvv[j], acc[i][j]);
        }
    }
    #pragma unroll
    for (int i = 0; i < 8; i++) {
        int q = ty * 8 + i;
        float4 v = {acc[i][0], acc[i][1], acc[i][2], acc[i][3]};
        *(float4*)(O + ((size_t)b * TT + q) * DD + h * HDIM + tx * 4) = v;
    }
}

// ------------------------- host orchestration -------------------------
extern "C" void kernel_launch(void* const* d_in, const int* in_sizes, int n_in,
                              void* d_out, int out_size) {
    const float* memory   = (const float*)d_in[0];
    const int*   targets  = (const int*)  d_in[1];
    const float* tok_emb  = (const float*)d_in[2];
    const float* pos_emb  = (const float*)d_in[3];
    const float* sa_qkv_w = (const float*)d_in[4];
    const float* sa_qkv_b = (const float*)d_in[5];
    const float* sa_out_w = (const float*)d_in[6];
    const float* sa_out_b = (const float*)d_in[7];
    const float* ca_q_w   = (const float*)d_in[8];
    const float* ca_q_b   = (const float*)d_in[9];
    const float* ca_kv_w  = (const float*)d_in[10];
    const float* ca_kv_b  = (const float*)d_in[11];
    const float* ca_out_w = (const float*)d_in[12];
    const float* ca_out_b = (const float*)d_in[13];
    const float* ffn1_w   = (const float*)d_in[14];
    const float* ffn1_b   = (const float*)d_in[15];
    const float* ffn2_w   = (const float*)d_in[16];
    const float* ffn2_b   = (const float*)d_in[17];
    const float* ln1_g    = (const float*)d_in[18];
    const float* ln1_b    = (const float*)d_in[19];
    const float* ln2_g    = (const float*)d_in[20];
    const float* ln2_b    = (const float*)d_in[21];
    const float* ln3_g    = (const float*)d_in[22];
    const float* ln3_b    = (const float*)d_in[23];
    const float* normf_g  = (const float*)d_in[24];
    const float* normf_b  = (const float*)d_in[25];
    const float* out_w    = (const float*)d_in[26];
    const float* out_b    = (const float*)d_in[27];
    float* out = (float*)d_out;
    (void)in_sizes; (void)n_in; (void)out_size;

    float *x, *h, *q, *qkv, *kv, *sc, *ctx, *ffn;
    cudaGetSymbolAddress((void**)&x,   g_x);
    cudaGetSymbolAddress((void**)&h,   g_h);
    cudaGetSymbolAddress((void**)&q,   g_q);
    cudaGetSymbolAddress((void**)&qkv, g_qkv);
    cudaGetSymbolAddress((void**)&kv,  g_kv);
    cudaGetSymbolAddress((void**)&sc,  g_sc);
    cudaGetSymbolAddress((void**)&ctx, g_ctx);
    cudaGetSymbolAddress((void**)&ffn, g_ffn);

    detect_k<<<1, 256>>>(targets);
    embed_k<<<BT, 128>>>(targets, tok_emb, pos_emb, x);

    for (int l = 0; l < LLAYERS; l++) {
        // ---- self-attention ----
        ln_k<<<BT, 128>>>(x, ln1_g + l * DD, ln1_b + l * DD, h);
        sgemm_k<0><<<dim3(3 * DD / 64, BT / 64), 256>>>(
            h, sa_qkv_w + (size_t)l * DD * 3 * DD, sa_qkv_b + (size_t)l * 3 * DD,
            nullptr, qkv, 3 * DD, DD);
        scores_k<<<dim3(1, BB * HH), 256>>>(
            qkv, 3 * DD, (size_t)TT * 3 * DD,
            qkv + DD, 3 * DD, (size_t)TT * 3 * DD, TT, 1, sc);
        softmax_k<<<BB * HH * TT, 128>>>(sc, TT);
        pv_k<<<BB * HH, 256>>>(sc, TT, qkv + 2 * DD, 3 * DD, (size_t)TT * 3 * DD, ctx);
        sgemm_k<1><<<dim3(DD / 64, BT / 64), 256>>>(
            ctx, sa_out_w + (size_t)l * DD * DD, sa_out_b + (size_t)l * DD,
            x, x, DD, DD);

        // ---- cross-attention ----
        ln_k<<<BT, 128>>>(x, ln2_g + l * DD, ln2_b + l * DD, h);
        sgemm_k<0><<<dim3(DD / 64, BT / 64), 256>>>(
            h, ca_q_w + (size_t)l * DD * DD, ca_q_b + (size_t)l * DD,
            nullptr, q, DD, DD);
        sgemm_k<0><<<dim3(2 * DD / 64, BMEM / 64), 256>>>(
            memory, ca_kv_w + (size_t)l * DD * 2 * DD, ca_kv_b + (size_t)l * 2 * DD,
            nullptr, kv, 2 * DD, DD);
        scores_k<<<dim3(MM / 128, BB * HH), 256>>>(
            q, DD, (size_t)TT * DD,
            kv, 2 * DD, (size_t)MM * 2 * DD, MM, 0, sc);
        softmax_k<<<BB * HH * TT, 128>>>(sc, MM);
        pv_k<<<BB * HH, 256>>>(sc, MM, kv + DD, 2 * DD, (size_t)MM * 2 * DD, ctx);
        sgemm_k<1><<<dim3(DD / 64, BT / 64), 256>>>(
            ctx, ca_out_w + (size_t)l * DD * DD, ca_out_b + (size_t)l * DD,
            x, x, DD, DD);

        // ---- FFN ----
        ln_k<<<BT, 128>>>(x, ln3_g + l * DD, ln3_b + l * DD, h);
        sgemm_k<2><<<dim3(4 * DD / 64, BT / 64), 256>>>(
            h, ffn1_w + (size_t)l * DD * 4 * DD, ffn1_b + (size_t)l * 4 * DD,
            nullptr, ffn, 4 * DD, DD);
        sgemm_k<1><<<dim3(DD / 64, BT / 64), 256>>>(
            ffn, ffn2_w + (size_t)l * 4 * DD * DD, ffn2_b + (size_t)l * DD,
            x, x, DD, 4 * DD);
    }

    ln_k<<<BT, 128>>>(x, normf_g, normf_b, h);
    sgemm_k<0><<<dim3(VV / 64, BT / 64), 256>>>(
        h, out_w, out_b, nullptr, out, VV, DD);
}

// round 11
// speedup vs baseline: 1.0089x; 1.0089x over previous
#include <cuda_runtime.h>
#include <math.h>

#define BB 16
#define MM 256
#define TT 128
#define DD 512
#define HH 8
#define LLAYERS 4
#define VV 32000
#define HDIM 64
#define BT (BB*TT)      /* 2048 */
#define BMEM (BB*MM)    /* 4096 */
#define NEGINF -1e9f

// ------------------------- scratch (device globals) -------------------------
__device__ float g_x  [BT * DD];
__device__ float g_h  [BT * DD];
__device__ float g_q  [BT * DD];
__device__ float g_qkv[BT * 3 * DD];
__device__ float g_kv [BMEM * 2 * DD];
__device__ float g_sc [BB * HH * TT * MM];
__device__ float g_ctx[BT * DD];
__device__ float g_ffn[BT * 4 * DD];
__device__ int   g_is64;

// ------------------------- dtype probe for targets -------------------------
// If targets are int64 (little-endian, values in [0,32000)), every odd int32
// word of the first 1024 elements is zero. If int32, they are random token
// ids — all-zero has probability ~(1/32000)^1000. Reads stay within 2048
// int32s, which is the buffer size even in the int32 case.
__global__ void detect_k(const int* __restrict__ t) {
    __shared__ int allzero;
    if (threadIdx.x == 0) allzero = 1;
    __syncthreads();
    for (int i = threadIdx.x; i < 1024; i += blockDim.x) {
        if (t[2 * i + 1] != 0) allzero = 0;   // benign race, only writes 0
    }
    __syncthreads();
    if (threadIdx.x == 0) g_is64 = allzero;
}

// ------------------------- embedding -------------------------
__global__ void embed_k(const int* __restrict__ tgt,
                        const float* __restrict__ tok,
                        const float* __restrict__ pos,
                        float* __restrict__ x) {
    int bt = blockIdx.x;
    int b = bt / TT, t = bt % TT;
    int idx;
    if (t == 0) {
        idx = VV;  // BOS
    } else {
        int j = b * TT + t - 1;
        idx = g_is64 ? tgt[2 * j] : tgt[j];
    }
    const float* tr = tok + (size_t)idx * DD;
    const float* pr = pos + (size_t)t * DD;
    float* xr = x + (size_t)bt * DD;
    for (int d = threadIdx.x * 4; d < DD; d += blockDim.x * 4) {
        float4 a = *(const float4*)(tr + d);
        float4 p = *(const float4*)(pr + d);
        a.x += p.x; a.y += p.y; a.z += p.z; a.w += p.w;
        *(float4*)(xr + d) = a;
    }
}

// ------------------------- layernorm (row of 512, 128 threads) -------------
__global__ void ln_k(const float* __restrict__ x,
                     const float* __restrict__ g,
                     const float* __restrict__ b,
                     float* __restrict__ o) {
    int row = blockIdx.x;
    int tid = threadIdx.x;
    const float* xr = x + (size_t)row * DD;
    int d = tid * 4;
    float4 v = *(const float4*)(xr + d);
    float s  = v.x + v.y + v.z + v.w;
    float sq = v.x * v.x + v.y * v.y + v.z * v.z + v.w * v.w;
    __shared__ float rs[32], rq[32];
    #pragma unroll
    for (int ofs = 16; ofs > 0; ofs >>= 1) {
        s  += __shfl_xor_sync(0xffffffffu, s, ofs);
        sq += __shfl_xor_sync(0xffffffffu, sq, ofs);
    }
    if ((tid & 31) == 0) { rs[tid >> 5] = s; rq[tid >> 5] = sq; }
    __syncthreads();
    float S = rs[0] + rs[1] + rs[2] + rs[3];
    float Q = rq[0] + rq[1] + rq[2] + rq[3];
    float mean = S * (1.0f / DD);
    float var  = Q * (1.0f / DD) - mean * mean;
    float rstd = rsqrtf(var + 1e-5f);
    float4 gg = *(const float4*)(g + d);
    float4 bb = *(const float4*)(b + d);
    float4 r;
    r.x = (v.x - mean) * rstd * gg.x + bb.x;
    r.y = (v.y - mean) * rstd * gg.y + bb.y;
    r.z = (v.z - mean) * rstd * gg.z + bb.z;
    r.w = (v.w - mean) * rstd * gg.w + bb.w;
    *(float4*)(o + (size_t)row * DD + d) = r;
}

// ------------------------- SGEMM: C = A[rows,K] @ W[K,Ncols] + epi ---------
// EPI: 0 = +bias, 1 = +bias+residual, 2 = +bias then exact GELU
// Requires: rows % 64 == 0 (via grid.y), Ncols % 64 == 0, K % 16 == 0.
template <int EPI>
__global__ void __launch_bounds__(256)
sgemm_k(const float* __restrict__ A, const float* __restrict__ W,
        const float* __restrict__ bias, const float* __restrict__ res,
        float* __restrict__ C, int Ncols, int K) {
    __shared__ float As[16][64];  // transposed: As[k][m]
    __shared__ float Bs[16][64];
    int tid = threadIdx.x;
    int tx = tid & 15, ty = tid >> 4;
    int rowBase = blockIdx.y * 64, colBase = blockIdx.x * 64;
    int am = tid >> 2, ak = (tid & 3) * 4;
    int bk = tid >> 4, bc = (tid & 15) * 4;
    const float* Ap = A + (size_t)(rowBase + am) * K + ak;
    const float* Wp = W + (size_t)bk * Ncols + colBase + bc;

    float acc[4][4];
    #pragma unroll
    for (int i = 0; i < 4; i++)
        #pragma unroll
        for (int j = 0; j < 4; j++) acc[i][j] = 0.0f;

    for (int k0 = 0; k0 < K; k0 += 16) {
        float4 av = *(const float4*)Ap; Ap += 16;
        float4 bv = *(const float4*)Wp; Wp += (size_t)16 * Ncols;
        __syncthreads();
        As[ak + 0][am] = av.x;
        As[ak + 1][am] = av.y;
        As[ak + 2][am] = av.z;
        As[ak + 3][am] = av.w;
        *(float4*)&Bs[bk][bc] = bv;
        __syncthreads();
        #pragma unroll
        for (int kk = 0; kk < 16; kk++) {
            float4 a4 = *(const float4*)&As[kk][ty * 4];
            float4 b4 = *(const float4*)&Bs[kk][tx * 4];
            float a[4] = {a4.x, a4.y, a4.z, a4.w};
            float b[4] = {b4.x, b4.y, b4.z, b4.w};
            #pragma unroll
            for (int i = 0; i < 4; i++)
                #pragma unroll
                for (int j = 0; j < 4; j++)
                    acc[i][j] = fmaf(a[i], b[j], acc[i][j]);
        }
    }

    int cBase = colBase + tx * 4;
    float4 bia = *(const float4*)(bias + cBase);
    #pragma unroll
    for (int i = 0; i < 4; i++) {
        int r = rowBase + ty * 4 + i;
        float4 v;
        v.x = acc[i][0] + bia.x;
        v.y = acc[i][1] + bia.y;
        v.z = acc[i][2] + bia.z;
        v.w = acc[i][3] + bia.w;
        if (EPI == 1) {
            float4 rr = *(const float4*)(res + (size_t)r * Ncols + cBase);
            v.x += rr.x; v.y += rr.y; v.z += rr.z; v.w += rr.w;
        }
        if (EPI == 2) {
            v.x = 0.5f * v.x * (1.0f + erff(v.x * 0.70710678118654752f));
            v.y = 0.5f * v.y * (1.0f + erff(v.y * 0.70710678118654752f));
            v.z = 0.5f * v.z * (1.0f + erff(v.z * 0.70710678118654752f));
            v.w = 0.5f * v.w * (1.0f + erff(v.w * 0.70710678118654752f));
        }
        *(float4*)(C + (size_t)r * Ncols + cBase) = v;
    }
}

// ------------------------- attention scores -------------------------
// S[bh, q, k] = scale * dot(Q[b,q,h,:], K[b,k,h,:]); causal mask optional.
// One block per (128-col tile, bh). Block 256 threads, 8x8 per thread.
__global__ void __launch_bounds__(256)
scores_k(const float* __restrict__ Qb, int qStride, size_t qBatch,
         const float* __restrict__ Kb, int kStride, size_t kBatch,
         int Lk, int causal, float* __restrict__ S) {
    int bh = blockIdx.y;
    int b = bh / HH, h = bh % HH;
    int k0 = blockIdx.x * 128;
    const float* Q  = Qb + (size_t)b * qBatch + h * HDIM;
    const float* Kp = Kb + (size_t)b * kBatch + h * HDIM;
    __shared__ float Qs[16][128];
    __shared__ float Ks[16][128];
    int tid = threadIdx.x;
    int tx = tid & 15, ty = tid >> 4;
    int lr = tid >> 1, ls = (tid & 1) * 8;

    float acc[8][8];
    #pragma unroll
    for (int i = 0; i < 8; i++)
        #pragma unroll
        for (int j = 0; j < 8; j++) acc[i][j] = 0.0f;

    for (int d0 = 0; d0 < HDIM; d0 += 16) {
        float4 qa = *(const float4*)(Q + (size_t)lr * qStride + d0 + ls);
        float4 qb = *(const float4*)(Q + (size_t)lr * qStride + d0 + ls + 4);
        float4 ka = *(const float4*)(Kp + (size_t)(k0 + lr) * kStride + d0 + ls);
        float4 kb = *(const float4*)(Kp + (size_t)(k0 + lr) * kStride + d0 + ls + 4);
        __syncthreads();
        Qs[ls + 0][lr] = qa.x; Qs[ls + 1][lr] = qa.y; Qs[ls + 2][lr] = qa.z; Qs[ls + 3][lr] = qa.w;
        Qs[ls + 4][lr] = qb.x; Qs[ls + 5][lr] = qb.y; Qs[ls + 6][lr] = qb.z; Qs[ls + 7][lr] = qb.w;
        Ks[ls + 0][lr] = ka.x; Ks[ls + 1][lr] = ka.y; Ks[ls + 2][lr] = ka.z; Ks[ls + 3][lr] = ka.w;
        Ks[ls + 4][lr] = kb.x; Ks[ls + 5][lr] = kb.y; Ks[ls + 6][lr] = kb.z; Ks[ls + 7][lr] = kb.w;
        __syncthreads();
        #pragma unroll
        for (int dd = 0; dd < 16; dd++) {
            float4 q0 = *(const float4*)&Qs[dd][ty * 8];
            float4 q1 = *(const float4*)&Qs[dd][ty * 8 + 4];
            float4 c0 = *(const float4*)&Ks[dd][tx * 8];
            float4 c1 = *(const float4*)&Ks[dd][tx * 8 + 4];
            float qv[8] = {q0.x, q0.y, q0.z, q0.w, q1.x, q1.y, q1.z, q1.w};
            float kv[8] = {c0.x, c0.y, c0.z, c0.w, c1.x, c1.y, c1.z, c1.w};
            #pragma unroll
            for (int i = 0; i < 8; i++)
                #pragma unroll
                for (int j = 0; j < 8; j++)
                    acc[i][j] = fmaf(qv[i], kv[j], acc[i][j]);
        }
    }
    const float scale = 0.125f;  // 1/sqrt(64)
    #pragma unroll
    for (int i = 0; i < 8; i++) {
        int q = ty * 8 + i;
        #pragma unroll
        for (int j = 0; j < 8; j++) {
            int kidx = k0 + tx * 8 + j;
            float v = acc[i][j] * scale;
            if (causal && kidx > q) v = NEGINF;
            S[((size_t)bh * TT + q) * Lk + kidx] = v;
        }
    }
}

// ------------------------- row softmax (in place) -------------------------
__global__ void softmax_k(float* __restrict__ S, int Lk) {
    int row = blockIdx.x;
    float* r = S + (size_t)row * Lk;
    int tid = threadIdx.x;  // 128
    __shared__ float red[32];

    float m = -3.4e38f;
    for (int i = tid; i < Lk; i += 128) m = fmaxf(m, r[i]);
    #pragma unroll
    for (int ofs = 16; ofs > 0; ofs >>= 1) m = fmaxf(m, __shfl_xor_sync(0xffffffffu, m, ofs));
    if ((tid & 31) == 0) red[tid >> 5] = m;
    __syncthreads();
    m = fmaxf(fmaxf(red[0], red[1]), fmaxf(red[2], red[3]));

    float s = 0.0f;
    for (int i = tid; i < Lk; i += 128) {
        float e = expf(r[i] - m);
        r[i] = e;
        s += e;
    }
    #pragma unroll
    for (int ofs = 16; ofs > 0; ofs >>= 1) s += __shfl_xor_sync(0xffffffffu, s, ofs);
    __syncthreads();
    if ((tid & 31) == 0) red[tid >> 5] = s;
    __syncthreads();
    s = red[0] + red[1] + red[2] + red[3];
    float inv = 1.0f / s;
    for (int i = tid; i < Lk; i += 128) r[i] *= inv;
}

// ------------------------- ctx = P @ V, written merged [B,T,D] -------------
__global__ void __launch_bounds__(256)
pv_k(const float* __restrict__ S, int Lk,
     const float* __restrict__ Vb, int vStride, size_t vBatch,
     float* __restrict__ O) {
    int bh = blockIdx.x;
    int b = bh / HH, h = bh % HH;
    const float* P  = S + (size_t)bh * TT * Lk;
    const float* Vp = Vb + (size_t)b * vBatch + h * HDIM;
    __shared__ float Ps[16][128];
    __shared__ float Vs[16][64];
    int tid = threadIdx.x;
    int tx = tid & 15, ty = tid >> 4;
    int pr = tid >> 1, ps = (tid & 1) * 8;
    int vk = tid >> 4, vc = (tid & 15) * 4;

    float acc[8][4];
    #pragma unroll
    for (int i = 0; i < 8; i++)
        #pragma unroll
        for (int j = 0; j < 4; j++) acc[i][j] = 0.0f;

    for (int k0 = 0; k0 < Lk; k0 += 16) {
        float4 pa = *(const float4*)(P + (size_t)pr * Lk + k0 + ps);
        float4 pb = *(const float4*)(P + (size_t)pr * Lk + k0 + ps + 4);
        float4 vv = *(const float4*)(Vp + (size_t)(k0 + vk) * vStride + vc);
        __syncthreads();
        Ps[ps + 0][pr] = pa.x; Ps[ps + 1][pr] = pa.y; Ps[ps + 2][pr] = pa.z; Ps[ps + 3][pr] = pa.w;
        Ps[ps + 4][pr] = pb.x; Ps[ps + 5][pr] = pb.y; Ps[ps + 6][pr] = pb.z; Ps[ps + 7][pr] = pb.w;
        *(float4*)&Vs[vk][vc] = vv;
        __syncthreads();
        #pragma unroll
        for (int kk = 0; kk < 16; kk++) {
            float4 p0 = *(const float4*)&Ps[kk][ty * 8];
            float4 p1 = *(const float4*)&Ps[kk][ty * 8 + 4];
            float4 v4 = *(const float4*)&Vs[kk][tx * 4];
            float pvv[8] = {p0.x, p0.y, p0.z, p0.w, p1.x, p1.y, p1.z, p1.w};
            float vvv[4] = {v4.x, v4.y, v4.z, v4.w};
            #pragma unroll
            for (int i = 0; i < 8; i++)
                #pragma unroll
                for (int j = 0; j < 4; j++)
                    acc[i][j] = fmaf(pvv[i], vvv[j], acc[i][j]);
        }
    }
    #pragma unroll
    for (int i = 0; i < 8; i++) {
        int q = ty * 8 + i;
        float4 v = {acc[i][0], acc[i][1], acc[i][2], acc[i][3]};
        *(float4*)(O + ((size_t)b * TT + q) * DD + h * HDIM + tx * 4) = v;
    }
}

// ------------------------- host orchestration -------------------------
extern "C" void kernel_launch(void* const* d_in, const int* in_sizes, int n_in,
                              void* d_out, int out_size) {
    const float* memory   = (const float*)d_in[0];
    const int*   targets  = (const int*)  d_in[1];
    const float* tok_emb  = (const float*)d_in[2];
    const float* pos_emb  = (const float*)d_in[3];
    const float* sa_qkv_w = (const float*)d_in[4];
    const float* sa_qkv_b = (const float*)d_in[5];
    const float* sa_out_w = (const float*)d_in[6];
    const float* sa_out_b = (const float*)d_in[7];
    const float* ca_q_w   = (const float*)d_in[8];
    const float* ca_q_b   = (const float*)d_in[9];
    const float* ca_kv_w  = (const float*)d_in[10];
    const float* ca_kv_b  = (const float*)d_in[11];
    const float* ca_out_w = (const float*)d_in[12];
    const float* ca_out_b = (const float*)d_in[13];
    const float* ffn1_w   = (const float*)d_in[14];
    const float* ffn1_b   = (const float*)d_in[15];
    const float* ffn2_w   = (const float*)d_in[16];
    const float* ffn2_b   = (const float*)d_in[17];
    const float* ln1_g    = (const float*)d_in[18];
    const float* ln1_b    = (const float*)d_in[19];
    const float* ln2_g    = (const float*)d_in[20];
    const float* ln2_b    = (const float*)d_in[21];
    const float* ln3_g    = (const float*)d_in[22];
    const float* ln3_b    = (const float*)d_in[23];
    const float* normf_g  = (const float*)d_in[24];
    const float* normf_b  = (const float*)d_in[25];
    const float* out_w    = (const float*)d_in[26];
    const float* out_b    = (const float*)d_in[27];
    float* out = (float*)d_out;
    (void)in_sizes; (void)n_in; (void)out_size;

    float *x, *h, *q, *qkv, *kv, *sc, *ctx, *ffn;
    cudaGetSymbolAddress((void**)&x,   g_x);
    cudaGetSymbolAddress((void**)&h,   g_h);
    cudaGetSymbolAddress((void**)&q,   g_q);
    cudaGetSymbolAddress((void**)&qkv, g_qkv);
    cudaGetSymbolAddress((void**)&kv,  g_kv);
    cudaGetSymbolAddress((void**)&sc,  g_sc);
    cudaGetSymbolAddress((void**)&ctx, g_ctx);
    cudaGetSymbolAddress((void**)&ffn, g_ffn);

    detect_k<<<1, 256>>>(targets);
    embed_k<<<BT, 128>>>(targets, tok_emb, pos_emb, x);

    for (int l = 0; l < LLAYERS; l++) {
        // ---- self-attention ----
        ln_k<<<BT, 128>>>(x, ln1_g + l * DD, ln1_b + l * DD, h);
        sgemm_k<0><<<dim3(3 * DD / 64, BT / 64), 256>>>(
            h, sa_qkv_w + (size_t)l * DD * 3 * DD, sa_qkv_b + (size_t)l * 3 * DD,
            nullptr, qkv, 3 * DD, DD);
        scores_k<<<dim3(1, BB * HH), 256>>>(
            qkv, 3 * DD, (size_t)TT * 3 * DD,
            qkv + DD, 3 * DD, (size_t)TT * 3 * DD, TT, 1, sc);
        softmax_k<<<BB * HH * TT, 128>>>(sc, TT);
        pv_k<<<BB * HH, 256>>>(sc, TT, qkv + 2 * DD, 3 * DD, (size_t)TT * 3 * DD, ctx);
        sgemm_k<1><<<dim3(DD / 64, BT / 64), 256>>>(
            ctx, sa_out_w + (size_t)l * DD * DD, sa_out_b + (size_t)l * DD,
            x, x, DD, DD);

        // ---- cross-attention ----
        ln_k<<<BT, 128>>>(x, ln2_g + l * DD, ln2_b + l * DD, h);
        sgemm_k<0><<<dim3(DD / 64, BT / 64), 256>>>(
            h, ca_q_w + (size_t)l * DD * DD, ca_q_b + (size_t)l * DD,
            nullptr, q, DD, DD);
        sgemm_k<0><<<dim3(2 * DD / 64, BMEM / 64), 256>>>(
            memory, ca_kv_w + (size_t)l * DD * 2 * DD, ca_kv_b + (size_t)l * 2 * DD,
            nullptr, kv, 2 * DD, DD);
        scores_k<<<dim3(MM / 128, BB * HH), 256>>>(
            q, DD, (size_t)TT * DD,
            kv, 2 * DD, (size_t)MM * 2 * DD, MM, 0, sc);
        softmax_k<<<BB * HH * TT, 128>>>(sc, MM);
        pv_k<<<BB * HH, 256>>>(sc, MM, kv + DD, 2 * DD, (size_t)MM * 2 * DD, ctx);
        sgemm_k<1><<<dim3(DD / 64, BT / 64), 256>>>(
            ctx, ca_out_w + (size_t)l * DD * DD, ca_out_b + (size_t)l * DD,
            x, x, DD, DD);

        // ---- FFN ----
        ln_k<<<BT, 128>>>(x, ln3_g + l * DD, ln3_b + l * DD, h);
        sgemm_k<2><<<dim3(4 * DD / 64, BT / 64), 256>>>(
            h, ffn1_w + (size_t)l * DD * 4 * DD, ffn1_b + (size_t)l * 4 * DD,
            nullptr, ffn, 4 * DD, DD);
        sgemm_k<1><<<dim3(DD / 64, BT / 64), 256>>>(
            ffn, ffn2_w + (size_t)l * 4 * DD * DD, ffn2_b + (size_t)l * DD,
            x, x, DD, 4 * DD);
    }

    ln_k<<<BT, 128>>>(x, normf_g, normf_b, h);
    sgemm_k<0><<<dim3(VV / 64, BT / 64), 256>>>(
        h, out_w, out_b, nullptr, out, VV, DD);
}